// round 1
// baseline (speedup 1.0000x reference)
#include <cuda_runtime.h>
#include <math.h>

#define NN 50000
#define EE 800000
#define HH 128
#define LL 4

// ---------------- scratch (static device globals; no allocation) -------------
__device__ float g_hw[(size_t)NN * HH];       // h @ W result per layer
__device__ float g_h[(size_t)NN * HH];        // activations between layers
__device__ int   g_cnt[NN];
__device__ int   g_cursor[NN];
__device__ int   g_rowstart[NN + 1];
__device__ float g_isd[NN];                   // 1/sqrt(deg)
__device__ float g_invd[NN];                  // 1/deg
__device__ int   g_srcs[EE];                  // CSR: src node per (dst-sorted) edge
__device__ float g_norms[EE];                 // CSR: isd[src]*isd[dst]

// ---------------- setup kernels ----------------------------------------------
__global__ void k_init() {
    int i = blockIdx.x * blockDim.x + threadIdx.x;
    if (i < NN) { g_cnt[i] = 0; g_cursor[i] = 0; }
}

__global__ void k_count(const int* __restrict__ dst) {
    int e = blockIdx.x * blockDim.x + threadIdx.x;
    if (e < EE) atomicAdd(&g_cnt[dst[e]], 1);
}

__global__ void k_invs() {
    int i = blockIdx.x * blockDim.x + threadIdx.x;
    if (i < NN) {
        float deg = (float)g_cnt[i] + 1.0f;   // +1 self loop
        g_isd[i]  = rsqrtf(deg);
        g_invd[i] = 1.0f / deg;
    }
}

// single-block exclusive scan over g_cnt -> g_rowstart (N+1 entries)
__global__ void k_scan() {
    __shared__ int ss[1024];
    const int IT = 49;                         // 1024*49 = 50176 >= 50001
    int t = threadIdx.x;
    int base = t * IT;
    int s = 0;
    for (int i = 0; i < IT; i++) {
        int idx = base + i;
        if (idx < NN) s += g_cnt[idx];
    }
    ss[t] = s;
    __syncthreads();
    for (int off = 1; off < 1024; off <<= 1) {
        int v = 0;
        if (t >= off) v = ss[t - off];
        __syncthreads();
        if (t >= off) ss[t] += v;
        __syncthreads();
    }
    int run = ss[t] - s;                       // exclusive prefix of this chunk
    for (int i = 0; i < IT; i++) {
        int idx = base + i;
        if (idx <= NN) {
            g_rowstart[idx] = run;
            if (idx < NN) run += g_cnt[idx];
        }
    }
}

__global__ void k_fill(const int* __restrict__ src, const int* __restrict__ dst) {
    int e = blockIdx.x * blockDim.x + threadIdx.x;
    if (e < EE) {
        int s = src[e], d = dst[e];
        int pos = atomicAdd(&g_cursor[d], 1);
        int idx = g_rowstart[d] + pos;
        g_srcs[idx]  = s;
        g_norms[idx] = g_isd[s] * g_isd[d];
    }
}

// ---------------- GEMM: g_hw = A (Nx128) @ W (128x128) -----------------------
// block: 256 threads, 64 rows x 128 cols per block.
// smem: full W (64KB) + A tile (32KB) -> dynamic smem 96KB.
__global__ void k_gemm(const float* __restrict__ A, const float* __restrict__ W) {
    extern __shared__ float sm[];
    float* sW = sm;                 // 128*128
    float* sA = sm + 128 * 128;     // 64*128
    int tid = threadIdx.x;

    // load W (16384 floats = 4096 float4)
    const float4* Wv = (const float4*)W;
    float4* sWv = (float4*)sW;
#pragma unroll
    for (int i = 0; i < 16; i++) sWv[tid + 256 * i] = Wv[tid + 256 * i];

    int row0 = blockIdx.x * 64;
    int rows = NN - row0; if (rows > 64) rows = 64;

    const float4* Av = (const float4*)(A + (size_t)row0 * HH);
    float4* sAv = (float4*)sA;
    int tot4 = rows * 32;
    for (int i = tid; i < tot4; i += 256) sAv[i] = Av[i];
    __syncthreads();

    int tr = tid >> 5;          // row group 0..7 (one per warp)
    int cg = tid & 31;          // col group 0..31 -> cols cg*4..cg*4+3
    int rbase = tr * 8;

    float acc[8][4];
#pragma unroll
    for (int r = 0; r < 8; r++)
#pragma unroll
        for (int c = 0; c < 4; c++) acc[r][c] = 0.0f;

#pragma unroll 2
    for (int k = 0; k < 128; k += 4) {
        float4 b0 = *(const float4*)&sW[(k + 0) * 128 + cg * 4];
        float4 b1 = *(const float4*)&sW[(k + 1) * 128 + cg * 4];
        float4 b2 = *(const float4*)&sW[(k + 2) * 128 + cg * 4];
        float4 b3 = *(const float4*)&sW[(k + 3) * 128 + cg * 4];
#pragma unroll
        for (int r = 0; r < 8; r++) {
            float4 a = *(const float4*)&sA[(rbase + r) * 128 + k];  // broadcast across warp
            acc[r][0] += a.x * b0.x + a.y * b1.x + a.z * b2.x + a.w * b3.x;
            acc[r][1] += a.x * b0.y + a.y * b1.y + a.z * b2.y + a.w * b3.y;
            acc[r][2] += a.x * b0.z + a.y * b1.z + a.z * b2.z + a.w * b3.z;
            acc[r][3] += a.x * b0.w + a.y * b1.w + a.z * b2.w + a.w * b3.w;
        }
    }

#pragma unroll
    for (int r = 0; r < 8; r++) {
        int row = rbase + r;
        if (row < rows) {
            *(float4*)&g_hw[(size_t)(row0 + row) * HH + cg * 4] =
                make_float4(acc[r][0], acc[r][1], acc[r][2], acc[r][3]);
        }
    }
}

// ---------------- fused aggregate + bias + LayerNorm + GELU (+head) ----------
// one warp per node; lane l owns features [4l, 4l+4)
__global__ void k_agg(const float* __restrict__ cb, const float* __restrict__ lg,
                      const float* __restrict__ lb, float* __restrict__ hout,
                      int do_gelu, const float* __restrict__ head_w,
                      const float* __restrict__ head_b, float* __restrict__ scores) {
    int gwarp = (blockIdx.x * blockDim.x + threadIdx.x) >> 5;
    int lane = threadIdx.x & 31;
    if (gwarp >= NN) return;
    int v = gwarp;
    int c4 = lane * 4;

    int beg = g_rowstart[v];
    int end = g_rowstart[v + 1];

    float a0 = 0.f, a1 = 0.f, a2 = 0.f, a3 = 0.f;
    for (int e = beg; e < end; e++) {
        int s = g_srcs[e];
        float nrm = g_norms[e];
        float4 val = *(const float4*)&g_hw[(size_t)s * HH + c4];
        a0 += val.x * nrm; a1 += val.y * nrm; a2 += val.z * nrm; a3 += val.w * nrm;
    }
    // self loop
    float invd = g_invd[v];
    float4 sv = *(const float4*)&g_hw[(size_t)v * HH + c4];
    a0 += sv.x * invd; a1 += sv.y * invd; a2 += sv.z * invd; a3 += sv.w * invd;
    // conv bias
    float4 bb = *(const float4*)&cb[c4];
    a0 += bb.x; a1 += bb.y; a2 += bb.z; a3 += bb.w;

    // layernorm over 128 features
    float sum = a0 + a1 + a2 + a3;
    float sq  = a0 * a0 + a1 * a1 + a2 * a2 + a3 * a3;
#pragma unroll
    for (int off = 16; off > 0; off >>= 1) {
        sum += __shfl_xor_sync(0xffffffffu, sum, off);
        sq  += __shfl_xor_sync(0xffffffffu, sq, off);
    }
    float mu = sum * (1.0f / 128.0f);
    float var = sq * (1.0f / 128.0f) - mu * mu;
    float rstd = rsqrtf(var + 1e-5f);

    float4 gg = *(const float4*)&lg[c4];
    float4 bl = *(const float4*)&lb[c4];
    a0 = (a0 - mu) * rstd * gg.x + bl.x;
    a1 = (a1 - mu) * rstd * gg.y + bl.y;
    a2 = (a2 - mu) * rstd * gg.z + bl.z;
    a3 = (a3 - mu) * rstd * gg.w + bl.w;

    if (do_gelu) {
        const float inv_sqrt2 = 0.7071067811865475f;
        a0 = 0.5f * a0 * (1.0f + erff(a0 * inv_sqrt2));
        a1 = 0.5f * a1 * (1.0f + erff(a1 * inv_sqrt2));
        a2 = 0.5f * a2 * (1.0f + erff(a2 * inv_sqrt2));
        a3 = 0.5f * a3 * (1.0f + erff(a3 * inv_sqrt2));
    }

    *(float4*)&hout[(size_t)v * HH + c4] = make_float4(a0, a1, a2, a3);

    if (scores) {
        float4 w = *(const float4*)&head_w[c4];
        float sc = a0 * w.x + a1 * w.y + a2 * w.z + a3 * w.w;
#pragma unroll
        for (int off = 16; off > 0; off >>= 1)
            sc += __shfl_xor_sync(0xffffffffu, sc, off);
        if (lane == 0) scores[v] = sc + head_b[0];
    }
}

// ---------------- launch ------------------------------------------------------
extern "C" void kernel_launch(void* const* d_in, const int* in_sizes, int n_in,
                              void* d_out, int out_size) {
    const float* x      = (const float*)d_in[0];
    const int*   ei     = (const int*)  d_in[1];
    const float* conv_w = (const float*)d_in[2];
    const float* conv_b = (const float*)d_in[3];
    const float* ln_g   = (const float*)d_in[4];
    const float* ln_b   = (const float*)d_in[5];
    const float* head_w = (const float*)d_in[6];
    const float* head_b = (const float*)d_in[7];
    float* out = (float*)d_out;            // [0,N) scores, [N, N+N*128) h

    const int* src = ei;
    const int* dst = ei + EE;

    static const int GEMM_SMEM = (128 * 128 + 64 * 128) * (int)sizeof(float); // 96KB
    cudaFuncSetAttribute(k_gemm, cudaFuncAttributeMaxDynamicSharedMemorySize, GEMM_SMEM);

    void* h_dev = nullptr;
    cudaGetSymbolAddress(&h_dev, g_h);

    k_init <<<(NN + 255) / 256, 256>>> ();
    k_count<<<(EE + 255) / 256, 256>>> (dst);
    k_invs <<<(NN + 255) / 256, 256>>> ();
    k_scan <<<1, 1024>>> ();
    k_fill <<<(EE + 255) / 256, 256>>> (src, dst);

    for (int l = 0; l < LL; l++) {
        const float* A = (l == 0) ? x : (const float*)h_dev;
        k_gemm<<<(NN + 63) / 64, 256, GEMM_SMEM>>>(A, conv_w + (size_t)l * HH * HH);

        bool last = (l == LL - 1);
        float* hout = last ? (out + NN) : (float*)h_dev;
        k_agg<<<(NN * 32 + 255) / 256, 256>>>(
            conv_b + (size_t)l * HH, ln_g + (size_t)l * HH, ln_b + (size_t)l * HH,
            hout, last ? 0 : 1, head_w, head_b, last ? out : nullptr);
    }
}

// round 2
// speedup vs baseline: 1.2725x; 1.2725x over previous
#include <cuda_runtime.h>
#include <math.h>
#include <stdint.h>

#define NN 50000
#define EE 800000
#define HH 128
#define LL 4
#define SB 196   // scan blocks = ceil(NN/256)

// ---------------- scratch (static device globals; no allocation) -------------
__device__ float g_hw[(size_t)NN * HH];       // h @ W result per layer
__device__ float g_h[(size_t)NN * HH];        // activations between layers
__device__ int   g_cnt[NN];
__device__ int   g_cursor[NN];
__device__ int   g_rowstart[NN + 1];
__device__ float g_isd[NN];                   // 1/sqrt(deg)
__device__ float g_invd[NN];                  // 1/deg
__device__ int   g_srcs[EE];                  // CSR: src node per (dst-sorted) edge
__device__ float g_norms[EE];                 // CSR: isd[src]*isd[dst]
__device__ int   g_part[256];                 // scan partials

// ---------------- setup kernels ----------------------------------------------
__global__ void k_init() {
    int i = blockIdx.x * blockDim.x + threadIdx.x;
    if (i < NN) { g_cnt[i] = 0; g_cursor[i] = 0; }
}

__global__ void k_count(const int* __restrict__ dst) {
    int e = blockIdx.x * blockDim.x + threadIdx.x;
    if (e < EE) atomicAdd(&g_cnt[dst[e]], 1);
}

// ---- fast 3-kernel scan over g_cnt -> g_rowstart ----
__global__ void k_blocksum() {
    int i = blockIdx.x * 256 + threadIdx.x;
    int v = (i < NN) ? g_cnt[i] : 0;
    int lane = threadIdx.x & 31, w = threadIdx.x >> 5;
    __shared__ int ws[8];
#pragma unroll
    for (int o = 16; o > 0; o >>= 1) v += __shfl_down_sync(0xffffffffu, v, o);
    if (lane == 0) ws[w] = v;
    __syncthreads();
    if (threadIdx.x == 0) {
        int s = 0;
#pragma unroll
        for (int j = 0; j < 8; j++) s += ws[j];
        g_part[blockIdx.x] = s;
    }
}

__global__ void k_scanpart() {
    int t = threadIdx.x;
    int v = (t < SB) ? g_part[t] : 0;
    int lane = t & 31, w = t >> 5;
    int x = v;
#pragma unroll
    for (int o = 1; o < 32; o <<= 1) {
        int y = __shfl_up_sync(0xffffffffu, x, o);
        if (lane >= o) x += y;
    }
    __shared__ int ws[8];
    if (lane == 31) ws[w] = x;
    __syncthreads();
    if (t == 0) {
        int run = 0;
#pragma unroll
        for (int j = 0; j < 8; j++) { int tmp = ws[j]; ws[j] = run; run += tmp; }
    }
    __syncthreads();
    int incl = x + ws[w];
    if (t < SB) g_part[t] = incl - v;   // exclusive prefix of block sums
}

__global__ void k_blockscan() {
    int b = blockIdx.x;
    int i = b * 256 + threadIdx.x;
    int v = (i < NN) ? g_cnt[i] : 0;
    int lane = threadIdx.x & 31, w = threadIdx.x >> 5;
    int x = v;
#pragma unroll
    for (int o = 1; o < 32; o <<= 1) {
        int y = __shfl_up_sync(0xffffffffu, x, o);
        if (lane >= o) x += y;
    }
    __shared__ int ws[8];
    if (lane == 31) ws[w] = x;
    __syncthreads();
    if (threadIdx.x == 0) {
        int run = 0;
#pragma unroll
        for (int j = 0; j < 8; j++) { int tmp = ws[j]; ws[j] = run; run += tmp; }
    }
    __syncthreads();
    int incl = x + ws[w];
    int ex = incl - v;
    int base = g_part[b];
    if (i < NN) {
        g_rowstart[i] = base + ex;
        float deg = (float)v + 1.0f;
        g_isd[i]  = rsqrtf(deg);
        g_invd[i] = 1.0f / deg;
    }
    if (i == NN - 1) g_rowstart[NN] = base + ex + v;
}

__global__ void k_fill(const int* __restrict__ src, const int* __restrict__ dst) {
    int e = blockIdx.x * blockDim.x + threadIdx.x;
    if (e < EE) {
        int s = src[e], d = dst[e];
        int pos = atomicAdd(&g_cursor[d], 1);
        int idx = g_rowstart[d] + pos;
        g_srcs[idx]  = s;
        g_norms[idx] = g_isd[s] * g_isd[d];
    }
}

// ---------------- 3xTF32 tensor-core GEMM: g_hw = A (Nx128) @ W (128x128) ----
// Block: 256 threads (8 warps), tile 128 rows x 128 cols, K split in two halves.
// Smem per half: A hi/lo [128][68], W hi/lo [64][136] (padded, conflict-free).

#define SA_STRIDE 68
#define SW_STRIDE 136
#define SA_ELEMS (128 * SA_STRIDE)
#define SW_ELEMS (64 * SW_STRIDE)
#define GEMM_SMEM_FLOATS (2 * SA_ELEMS + 2 * SW_ELEMS)

__device__ __forceinline__ void tf32_split(float x, float& hi, float& lo) {
    unsigned h, l;
    asm("cvt.rna.tf32.f32 %0, %1;" : "=r"(h) : "f"(x));
    float r = x - __uint_as_float(h);
    asm("cvt.rna.tf32.f32 %0, %1;" : "=r"(l) : "f"(r));
    hi = __uint_as_float(h);
    lo = __uint_as_float(l);
}

#define MMA8(d, a, b) \
    asm volatile("mma.sync.aligned.m16n8k8.row.col.f32.tf32.tf32.f32 " \
                 "{%0,%1,%2,%3},{%4,%5,%6,%7},{%8,%9},{%0,%1,%2,%3};" \
                 : "+f"(d[0]), "+f"(d[1]), "+f"(d[2]), "+f"(d[3]) \
                 : "r"(a[0]), "r"(a[1]), "r"(a[2]), "r"(a[3]), "r"(b[0]), "r"(b[1]))

__global__ void __launch_bounds__(256, 1)
k_gemm_tc(const float* __restrict__ A, const float* __restrict__ W) {
    extern __shared__ float sm[];
    float* sAh = sm;
    float* sAl = sm + SA_ELEMS;
    float* sWh = sm + 2 * SA_ELEMS;
    float* sWl = sm + 2 * SA_ELEMS + SW_ELEMS;
    const unsigned* sAh_u = (const unsigned*)sAh;
    const unsigned* sAl_u = (const unsigned*)sAl;
    const unsigned* sWh_u = (const unsigned*)sWh;
    const unsigned* sWl_u = (const unsigned*)sWl;

    const int tid = threadIdx.x;
    const int lane = tid & 31, warp = tid >> 5;
    const int wm = warp >> 2, wn = warp & 3;   // wm 0..1, wn 0..3
    const int g = lane >> 2, t4 = lane & 3;
    const int row0 = blockIdx.x * 128;

    float acc[4][4][4];
#pragma unroll
    for (int mt = 0; mt < 4; mt++)
#pragma unroll
        for (int nt = 0; nt < 4; nt++)
#pragma unroll
            for (int c = 0; c < 4; c++) acc[mt][nt][c] = 0.0f;

    const float4* Wv = (const float4*)W;

    for (int half = 0; half < 2; half++) {
        const int k0 = half * 64;
        __syncthreads();
        // stage A rows [row0, row0+128), cols [k0, k0+64)
#pragma unroll
        for (int j = 0; j < 8; j++) {
            int idx = tid + 256 * j;
            int r = idx >> 4, c = idx & 15;
            int grow = row0 + r;
            float4 v = make_float4(0.f, 0.f, 0.f, 0.f);
            if (grow < NN) v = *(const float4*)&A[(size_t)grow * HH + k0 + c * 4];
            float4 hv, lv;
            tf32_split(v.x, hv.x, lv.x);
            tf32_split(v.y, hv.y, lv.y);
            tf32_split(v.z, hv.z, lv.z);
            tf32_split(v.w, hv.w, lv.w);
            *(float4*)&sAh[r * SA_STRIDE + c * 4] = hv;
            *(float4*)&sAl[r * SA_STRIDE + c * 4] = lv;
        }
        // stage W rows [k0, k0+64), all 128 cols
#pragma unroll
        for (int j = 0; j < 8; j++) {
            int idx = tid + 256 * j;
            int kr = idx >> 5, c = idx & 31;
            float4 v = Wv[(size_t)(k0 + kr) * 32 + c];
            float4 hv, lv;
            tf32_split(v.x, hv.x, lv.x);
            tf32_split(v.y, hv.y, lv.y);
            tf32_split(v.z, hv.z, lv.z);
            tf32_split(v.w, hv.w, lv.w);
            *(float4*)&sWh[kr * SW_STRIDE + c * 4] = hv;
            *(float4*)&sWl[kr * SW_STRIDE + c * 4] = lv;
        }
        __syncthreads();

        for (int ks = 0; ks < 8; ks++) {
            unsigned ah[4][4], al[4][4];
#pragma unroll
            for (int mt = 0; mt < 4; mt++) {
                int rb = (wm * 64 + mt * 16 + g) * SA_STRIDE;
                int col = ks * 8 + t4;
                ah[mt][0] = sAh_u[rb + col];
                ah[mt][1] = sAh_u[rb + 8 * SA_STRIDE + col];
                ah[mt][2] = sAh_u[rb + col + 4];
                ah[mt][3] = sAh_u[rb + 8 * SA_STRIDE + col + 4];
                al[mt][0] = sAl_u[rb + col];
                al[mt][1] = sAl_u[rb + 8 * SA_STRIDE + col];
                al[mt][2] = sAl_u[rb + col + 4];
                al[mt][3] = sAl_u[rb + 8 * SA_STRIDE + col + 4];
            }
            unsigned bh[4][2], bl[4][2];
#pragma unroll
            for (int nt = 0; nt < 4; nt++) {
                int n = wn * 32 + nt * 8 + g;
                int kr = (ks * 8 + t4) * SW_STRIDE;
                bh[nt][0] = sWh_u[kr + n];
                bh[nt][1] = sWh_u[kr + 4 * SW_STRIDE + n];
                bl[nt][0] = sWl_u[kr + n];
                bl[nt][1] = sWl_u[kr + 4 * SW_STRIDE + n];
            }
#pragma unroll
            for (int mt = 0; mt < 4; mt++)
#pragma unroll
                for (int nt = 0; nt < 4; nt++) {
                    MMA8(acc[mt][nt], al[mt], bh[nt]);
                    MMA8(acc[mt][nt], ah[mt], bl[nt]);
                    MMA8(acc[mt][nt], ah[mt], bh[nt]);
                }
        }
    }

    // store C fragments
#pragma unroll
    for (int mt = 0; mt < 4; mt++) {
#pragma unroll
        for (int nt = 0; nt < 4; nt++) {
            int row = row0 + wm * 64 + mt * 16 + g;
            int col = wn * 32 + nt * 8 + t4 * 2;
            if (row < NN)
                *(float2*)&g_hw[(size_t)row * HH + col] =
                    make_float2(acc[mt][nt][0], acc[mt][nt][1]);
            if (row + 8 < NN)
                *(float2*)&g_hw[(size_t)(row + 8) * HH + col] =
                    make_float2(acc[mt][nt][2], acc[mt][nt][3]);
        }
    }
}

// ---------------- fused aggregate + bias + LayerNorm + GELU (+head) ----------
// one warp per node; lane l owns features [4l, 4l+4)
__global__ void k_agg(const float* __restrict__ cb, const float* __restrict__ lg,
                      const float* __restrict__ lb, float* __restrict__ hout,
                      int do_gelu, const float* __restrict__ head_w,
                      const float* __restrict__ head_b, float* __restrict__ scores) {
    int gwarp = (blockIdx.x * blockDim.x + threadIdx.x) >> 5;
    int lane = threadIdx.x & 31;
    if (gwarp >= NN) return;
    int v = gwarp;
    int c4 = lane * 4;

    int beg = g_rowstart[v];
    int end = g_rowstart[v + 1];

    float a0 = 0.f, a1 = 0.f, a2 = 0.f, a3 = 0.f;
    for (int e = beg; e < end; e++) {
        int s = g_srcs[e];
        float nrm = g_norms[e];
        float4 val = *(const float4*)&g_hw[(size_t)s * HH + c4];
        a0 += val.x * nrm; a1 += val.y * nrm; a2 += val.z * nrm; a3 += val.w * nrm;
    }
    float invd = g_invd[v];
    float4 sv = *(const float4*)&g_hw[(size_t)v * HH + c4];
    a0 += sv.x * invd; a1 += sv.y * invd; a2 += sv.z * invd; a3 += sv.w * invd;
    float4 bb = *(const float4*)&cb[c4];
    a0 += bb.x; a1 += bb.y; a2 += bb.z; a3 += bb.w;

    float sum = a0 + a1 + a2 + a3;
    float sq  = a0 * a0 + a1 * a1 + a2 * a2 + a3 * a3;
#pragma unroll
    for (int off = 16; off > 0; off >>= 1) {
        sum += __shfl_xor_sync(0xffffffffu, sum, off);
        sq  += __shfl_xor_sync(0xffffffffu, sq, off);
    }
    float mu = sum * (1.0f / 128.0f);
    float var = sq * (1.0f / 128.0f) - mu * mu;
    float rstd = rsqrtf(var + 1e-5f);

    float4 gg = *(const float4*)&lg[c4];
    float4 bl = *(const float4*)&lb[c4];
    a0 = (a0 - mu) * rstd * gg.x + bl.x;
    a1 = (a1 - mu) * rstd * gg.y + bl.y;
    a2 = (a2 - mu) * rstd * gg.z + bl.z;
    a3 = (a3 - mu) * rstd * gg.w + bl.w;

    if (do_gelu) {
        const float inv_sqrt2 = 0.7071067811865475f;
        a0 = 0.5f * a0 * (1.0f + erff(a0 * inv_sqrt2));
        a1 = 0.5f * a1 * (1.0f + erff(a1 * inv_sqrt2));
        a2 = 0.5f * a2 * (1.0f + erff(a2 * inv_sqrt2));
        a3 = 0.5f * a3 * (1.0f + erff(a3 * inv_sqrt2));
    }

    *(float4*)&hout[(size_t)v * HH + c4] = make_float4(a0, a1, a2, a3);

    if (scores) {
        float4 w = *(const float4*)&head_w[c4];
        float sc = a0 * w.x + a1 * w.y + a2 * w.z + a3 * w.w;
#pragma unroll
        for (int off = 16; off > 0; off >>= 1)
            sc += __shfl_xor_sync(0xffffffffu, sc, off);
        if (lane == 0) scores[v] = sc + head_b[0];
    }
}

// ---------------- launch ------------------------------------------------------
extern "C" void kernel_launch(void* const* d_in, const int* in_sizes, int n_in,
                              void* d_out, int out_size) {
    const float* x      = (const float*)d_in[0];
    const int*   ei     = (const int*)  d_in[1];
    const float* conv_w = (const float*)d_in[2];
    const float* conv_b = (const float*)d_in[3];
    const float* ln_g   = (const float*)d_in[4];
    const float* ln_b   = (const float*)d_in[5];
    const float* head_w = (const float*)d_in[6];
    const float* head_b = (const float*)d_in[7];
    float* out = (float*)d_out;            // [0,N) scores, [N, N+N*128) h

    const int* src = ei;
    const int* dst = ei + EE;

    static const int GEMM_SMEM = GEMM_SMEM_FLOATS * (int)sizeof(float); // ~136KB
    cudaFuncSetAttribute(k_gemm_tc, cudaFuncAttributeMaxDynamicSharedMemorySize, GEMM_SMEM);

    void* h_dev = nullptr;
    cudaGetSymbolAddress(&h_dev, g_h);

    k_init     <<<(NN + 255) / 256, 256>>> ();
    k_count    <<<(EE + 255) / 256, 256>>> (dst);
    k_blocksum <<<SB, 256>>> ();
    k_scanpart <<<1, 256>>> ();
    k_blockscan<<<SB, 256>>> ();
    k_fill     <<<(EE + 255) / 256, 256>>> (src, dst);

    for (int l = 0; l < LL; l++) {
        const float* A = (l == 0) ? x : (const float*)h_dev;
        k_gemm_tc<<<(NN + 127) / 128, 256, GEMM_SMEM>>>(A, conv_w + (size_t)l * HH * HH);

        bool last = (l == LL - 1);
        float* hout = last ? (out + NN) : (float*)h_dev;
        k_agg<<<(NN * 32 + 255) / 256, 256>>>(
            conv_b + (size_t)l * HH, ln_g + (size_t)l * HH, ln_b + (size_t)l * HH,
            hout, last ? 0 : 1, head_w, head_b, last ? out : nullptr);
    }
}